// round 9
// baseline (speedup 1.0000x reference)
#include <cuda_runtime.h>
#include <cstdint>
#include <cstddef>

// segments (R6 layout): L1: (m<<10)+(c<<7)+o -> [0,2048), len 128
//  W2: 2048+o (128 segs, len 512)  W3: 2176+o (64)  Wout: 2240+o (128)
#define NSEG     2368
#define SEG_W2   2048
#define SEG_W3   2176
#define SEG_WOUT 2240
#define LIST_MAX 458752
#define LIST_CAP 16384
#define ACTS     1.3333333730697632f
#define THREADS  1024
#define GRID     256

__device__ int d_scale_bits[5];
__device__ int d_cnt[NSEG];
__device__ int d_off[NSEG + 1];
__device__ __align__(16) unsigned short d_list[LIST_MAX];

__global__ void prep_scale(const float* __restrict__ W1a, const float* __restrict__ W1b,
                           const float* __restrict__ W2,  const float* __restrict__ W3,
                           const float* __restrict__ Wout)
{
    __shared__ float red[8];
    int m = blockIdx.x >> 5, part = blockIdx.x & 31;
    const float* W; int n;
    switch (m) {
        case 0: W = W1a;  n = 131072; break;
        case 1: W = W1b;  n = 131072; break;
        case 2: W = W2;   n = 65536;  break;
        case 3: W = W3;   n = 8192;   break;
        default: W = Wout; n = 8192;  break;
    }
    int chunk = n >> 5, lo = part * chunk;
    float mx = 0.0f;
    for (int i = lo + threadIdx.x; i < lo + chunk; i += 256)
        mx = fmaxf(mx, fabsf(W[i]));
    #pragma unroll
    for (int o = 16; o; o >>= 1) mx = fmaxf(mx, __shfl_xor_sync(~0u, mx, o));
    if ((threadIdx.x & 31) == 0) red[threadIdx.x >> 5] = mx;
    __syncthreads();
    if (threadIdx.x < 32) {
        float v = (threadIdx.x < 8) ? red[threadIdx.x] : 0.0f;
        #pragma unroll
        for (int o = 4; o; o >>= 1) v = fmaxf(v, __shfl_xor_sync(~0u, v, o));
        if (threadIdx.x == 0) atomicMax(&d_scale_bits[m], __float_as_int(v));
    }
}

struct SegInfo { const float* rowp; int len; float s; bool l1; };

__device__ __forceinline__ SegInfo seg_decode(int seg,
    const float* W1a, const float* W1b, const float* W2,
    const float* W3, const float* Wout)
{
    SegInfo r;
    if (seg < SEG_W2) {
        int m = seg >> 10, rem = seg & 1023, c = rem >> 7, o = rem & 127;
        r.rowp = (m ? W1b : W1a) + o * 1024 + c * 128;
        r.len = 128; r.s = __int_as_float(d_scale_bits[m]); r.l1 = true;
    } else if (seg < SEG_W3) {
        r.rowp = W2 + (seg - SEG_W2) * 512;
        r.len = 512; r.s = __int_as_float(d_scale_bits[2]); r.l1 = false;
    } else if (seg < SEG_WOUT) {
        r.rowp = W3 + (seg - SEG_W3) * 128;
        r.len = 128; r.s = __int_as_float(d_scale_bits[3]); r.l1 = false;
    } else {
        r.rowp = Wout + (seg - SEG_WOUT) * 64;
        r.len = 64; r.s = __int_as_float(d_scale_bits[4]); r.l1 = false;
    }
    return r;
}

// counts: L1 padded to multiple of 4 (min 4); layers 2-4 exact (R6 behavior)
__global__ void prep_count(const float* __restrict__ W1a, const float* __restrict__ W1b,
                           const float* __restrict__ W2,  const float* __restrict__ W3,
                           const float* __restrict__ Wout)
{
    int lane = threadIdx.x & 31;
    int seg = blockIdx.x * 8 + (threadIdx.x >> 5);
    if (seg >= NSEG) return;
    SegInfo si = seg_decode(seg, W1a, W1b, W2, W3, Wout);
    int cnt = 0;
    for (int j0 = 0; j0 < si.len; j0 += 32) {
        float q = rintf(__fdiv_rn(si.rowp[j0 + lane], si.s));
        cnt += __popc(__ballot_sync(~0u, q != 0.0f));
    }
    if (lane == 0) {
        if (si.l1) {
            int pad = (cnt + 3) & ~3;
            d_cnt[seg] = pad ? pad : 4;
        } else {
            d_cnt[seg] = cnt;
        }
    }
}

// entries: L1: idx*33 | neg<<15  (pad = 4224 = 128*33, points at zero column)
//          others (R6): idx*72 | neg
__global__ void prep_scanfill(const float* __restrict__ W1a, const float* __restrict__ W1b,
                              const float* __restrict__ W2,  const float* __restrict__ W3,
                              const float* __restrict__ Wout)
{
    __shared__ int s_off[NSEG + 1];
    __shared__ int warpsum[8];
    int tid = threadIdx.x, lane = tid & 31, w = tid >> 5;
    {
        int base = tid * 10, v[10], s = 0;
        #pragma unroll
        for (int k = 0; k < 10; k++) {
            int idx = base + k;
            int c = (idx < NSEG) ? d_cnt[idx] : 0;
            v[k] = s; s += c;
        }
        int incl = s;
        #pragma unroll
        for (int o = 1; o < 32; o <<= 1) {
            int t = __shfl_up_sync(~0u, incl, o);
            if (lane >= o) incl += t;
        }
        if (lane == 31) warpsum[w] = incl;
        __syncthreads();
        if (w == 0 && lane < 8) {
            int ws = warpsum[lane];
            #pragma unroll
            for (int o = 1; o < 8; o <<= 1) {
                int t = __shfl_up_sync(0xffu, ws, o);
                if (lane >= o) ws += t;
            }
            warpsum[lane] = ws;
        }
        __syncthreads();
        int excl = incl - s + (w ? warpsum[w - 1] : 0);
        #pragma unroll
        for (int k = 0; k < 10; k++) {
            int idx = base + k;
            if (idx <= NSEG) s_off[idx] = excl + v[k];
        }
        __syncthreads();
    }
    if (blockIdx.x == 0)
        for (int i = tid; i <= NSEG; i += 256) d_off[i] = s_off[i];

    for (int seg = blockIdx.x * 8 + w; seg < NSEG; seg += gridDim.x * 8) {
        SegInfo si = seg_decode(seg, W1a, W1b, W2, W3, Wout);
        int base = s_off[seg];
        for (int j0 = 0; j0 < si.len; j0 += 32) {
            float q = rintf(__fdiv_rn(si.rowp[j0 + lane], si.s));
            bool nz = (q != 0.0f);
            unsigned bal = __ballot_sync(~0u, nz);
            if (nz) {
                int pos = base + __popc(bal & ((1u << lane) - 1u));
                int idx = j0 + lane;
                int neg = (q < 0.0f) ? 1 : 0;
                unsigned e = si.l1 ? (unsigned)(idx * 33 | (neg << 15))
                                   : (unsigned)((idx * 72) | neg);
                d_list[pos] = (unsigned short)e;
            }
            base += __popc(bal);
        }
        if (si.l1) {
            int end = s_off[seg + 1];
            for (int p = base + lane; p < end; p += 32) d_list[p] = (unsigned short)4224;
        }
    }
}

// smem: XS0@0:68112 (129 cols x 132 rows x 4B; col 128 = zero col)
//       XS1@68112 (end 136224)  H1@136224:18432(end 154656)
//       H2@154656:4608(end 159264)  H3@159264:2304(end 161568)
//       OFF@161568:9476(end 171044)  LIST@171048:32768 -> 203816
#define SMEM_BYTES 203816

__device__ __forceinline__ float quant_relu_q(float y) {
    float qv = rintf(__fdiv_rn(y, ACTS));
    return fminf(fmaxf(qv, 0.0f), 3.0f);
}

#define MAC1(e) { \
    float4 v = *(const float4*)(curb + (((e) & 0x7fffu) << 4)); \
    float wv = __int_as_float(scb ^ (((e) << 16) & 0x80000000u)); \
    t0 = fmaf(wv, v.x, t0); t1 = fmaf(wv, v.y, t1); \
    t2 = fmaf(wv, v.z, t2); t3 = fmaf(wv, v.w, t3); }
#define MAC4(pk) { \
    unsigned _e0 = pk.x & 0xffffu, _e1 = pk.x >> 16, _e2 = pk.y & 0xffffu, _e3 = pk.y >> 16; \
    MAC1(_e0); MAC1(_e1); MAC1(_e2); MAC1(_e3); }

template<bool USE_SM>
__device__ __forceinline__ void mlp_body(
    unsigned char* smem,
    const float* __restrict__ x,
    const float* __restrict__ b1a, const float* __restrict__ b1b,
    const float* __restrict__ b2,  const float* __restrict__ b3,
    float* __restrict__ out, int row0)
{
    float* xs0 = (float*)(smem);
    float* xs1 = (float*)(smem + 68112);
    unsigned char* h1s = smem + 136224;
    unsigned char* h2s = smem + 154656;
    unsigned char* h3s = smem + 159264;
    int* s_off = (int*)(smem + 161568);
    const unsigned short* lst = USE_SM ? (const unsigned short*)(smem + 171048)
                                       : (const unsigned short*)d_list;
    float* outs = (float*)(smem);     // alias XS0, layout [o][row] stride 132

    const int tid = threadIdx.x, lane = tid & 31, g = tid >> 5;
    const int srow = tid & 127, sc4 = tid >> 7;
    const float* xrow = x + (size_t)(row0 + srow) * 4096 + (sc4 << 2);

    const unsigned sc1a = (unsigned)d_scale_bits[0];
    const unsigned sc1b = (unsigned)d_scale_bits[1];
    const float s2 = __int_as_float(d_scale_bits[2]);
    const float s3 = __int_as_float(d_scale_bits[3]);
    const float s4 = __int_as_float(d_scale_bits[4]);

    // zero column (col 128) in both x buffers — L1 pad entries read it
    if (tid < 132) { xs0[128 * 132 + tid] = 0.0f; xs1[128 * 132 + tid] = 0.0f; }

    float4 pf[4];
    #pragma unroll
    for (int k = 0; k < 4; k++) pf[k] = __ldcs((const float4*)(xrow + (k << 5)));
    #pragma unroll
    for (int k = 0; k < 4; k++) {
        int cb = (sc4 + (k << 3)) << 2;
        xs0[(cb + 0) * 132 + srow] = pf[k].x;
        xs0[(cb + 1) * 132 + srow] = pf[k].y;
        xs0[(cb + 2) * 132 + srow] = pf[k].z;
        xs0[(cb + 3) * 132 + srow] = pf[k].w;
    }
    __syncthreads();
    #pragma unroll
    for (int k = 0; k < 4; k++) pf[k] = __ldcs((const float4*)(xrow + 128 + (k << 5)));

    float a0[4], a1[4], a2[4], a3[4];
    #pragma unroll
    for (int j = 0; j < 4; j++) a0[j] = a1[j] = a2[j] = a3[j] = 0.0f;

    for (int t = 0; t < 32; ++t) {
        const int branch = t >> 3, c = t & 7, m = branch & 1;
        const char* curb = (const char*)((t & 1) ? xs1 : xs0) + (lane << 4);
        const unsigned scb = m ? sc1b : sc1a;

        #pragma unroll
        for (int j = 0; j < 4; j++) {
            int seg = (m << 10) + (c << 7) + (g << 2) + j;
            int p = s_off[seg], pe = s_off[seg + 1];
            float t0 = a0[j], t1 = a1[j], t2 = a2[j], t3 = a3[j];
            uint2 pk = *(const uint2*)(lst + p);
            MAC4(pk);
            for (p += 4; p < pe; p += 4) {
                pk = *(const uint2*)(lst + p);
                MAC4(pk);
            }
            a0[j] = t0; a1[j] = t1; a2[j] = t2; a3[j] = t3;
        }

        if (c == 7) {
            const float* bb = m ? b1b : b1a;
            #pragma unroll
            for (int j = 0; j < 4; j++) {
                int o = (g << 2) + j;
                float bv = bb[o];
                unsigned c0 = (unsigned)(int)quant_relu_q(a0[j] + bv);
                unsigned c1 = (unsigned)(int)quant_relu_q(a1[j] + bv);
                unsigned c2 = (unsigned)(int)quant_relu_q(a2[j] + bv);
                unsigned c3 = (unsigned)(int)quant_relu_q(a3[j] + bv);
                h1s[(branch * 128 + o) * 36 + lane] =
                    (unsigned char)(c0 | (c1 << 2) | (c2 << 4) | (c3 << 6));
                a0[j] = a1[j] = a2[j] = a3[j] = 0.0f;
            }
        }

        if (t + 1 < 32) {
            float* nxt = (t & 1) ? xs0 : xs1;
            #pragma unroll
            for (int k = 0; k < 4; k++) {
                int cb = (sc4 + (k << 3)) << 2;
                nxt[(cb + 0) * 132 + srow] = pf[k].x;
                nxt[(cb + 1) * 132 + srow] = pf[k].y;
                nxt[(cb + 2) * 132 + srow] = pf[k].z;
                nxt[(cb + 3) * 132 + srow] = pf[k].w;
            }
            __syncthreads();
            if (t + 2 < 32) {
                const float* xb = xrow + (t + 2) * 128;
                #pragma unroll
                for (int k = 0; k < 4; k++)
                    pf[k] = __ldcs((const float4*)(xb + (k << 5)));
            }
        }
    }
    __syncthreads();

    // ---- layer 2 (R6 verbatim) ----
    {
        const unsigned char* hr = h1s + lane;
        #pragma unroll
        for (int j = 0; j < 4; j++) {
            int o = (g << 2) + j;
            int seg = SEG_W2 + o;
            int p0 = s_off[seg], p1 = s_off[seg + 1];
            int i0 = 0, i1 = 0, i2 = 0, i3 = 0;
            for (int p = p0; p < p1; ++p) {
                unsigned e = lst[p];
                int b = hr[e >> 1];
                int c0 = b & 3, c1 = (b >> 2) & 3, c2 = (b >> 4) & 3, c3 = (b >> 6) & 3;
                if (e & 1u) { i0 -= c0; i1 -= c1; i2 -= c2; i3 -= c3; }
                else        { i0 += c0; i1 += c1; i2 += c2; i3 += c3; }
            }
            float bv = b2[o];
            unsigned q0 = (unsigned)(int)quant_relu_q(fmaf((float)i0 * ACTS, s2, bv));
            unsigned q1 = (unsigned)(int)quant_relu_q(fmaf((float)i1 * ACTS, s2, bv));
            unsigned q2 = (unsigned)(int)quant_relu_q(fmaf((float)i2 * ACTS, s2, bv));
            unsigned q3 = (unsigned)(int)quant_relu_q(fmaf((float)i3 * ACTS, s2, bv));
            h2s[o * 36 + lane] = (unsigned char)(q0 | (q1 << 2) | (q2 << 4) | (q3 << 6));
        }
    }
    __syncthreads();

    // ---- layer 3 (R6 verbatim) ----
    {
        const unsigned char* hr = h2s + lane;
        #pragma unroll
        for (int j = 0; j < 2; j++) {
            int o = (g << 1) + j;
            int seg = SEG_W3 + o;
            int p0 = s_off[seg], p1 = s_off[seg + 1];
            int i0 = 0, i1 = 0, i2 = 0, i3 = 0;
            for (int p = p0; p < p1; ++p) {
                unsigned e = lst[p];
                int b = hr[e >> 1];
                int c0 = b & 3, c1 = (b >> 2) & 3, c2 = (b >> 4) & 3, c3 = (b >> 6) & 3;
                if (e & 1u) { i0 -= c0; i1 -= c1; i2 -= c2; i3 -= c3; }
                else        { i0 += c0; i1 += c1; i2 += c2; i3 += c3; }
            }
            float bv = b3[o];
            unsigned q0 = (unsigned)(int)quant_relu_q(fmaf((float)i0 * ACTS, s3, bv));
            unsigned q1 = (unsigned)(int)quant_relu_q(fmaf((float)i1 * ACTS, s3, bv));
            unsigned q2 = (unsigned)(int)quant_relu_q(fmaf((float)i2 * ACTS, s3, bv));
            unsigned q3 = (unsigned)(int)quant_relu_q(fmaf((float)i3 * ACTS, s3, bv));
            h3s[o * 36 + lane] = (unsigned char)(q0 | (q1 << 2) | (q2 << 4) | (q3 << 6));
        }
    }
    __syncthreads();

    // ---- output layer (R6 verbatim) ----
    {
        const unsigned char* hr = h3s + lane;
        #pragma unroll
        for (int j = 0; j < 4; j++) {
            int o = (g << 2) + j;
            int seg = SEG_WOUT + o;
            int p0 = s_off[seg], p1 = s_off[seg + 1];
            int i0 = 0, i1 = 0, i2 = 0, i3 = 0;
            for (int p = p0; p < p1; ++p) {
                unsigned e = lst[p];
                int b = hr[e >> 1];
                int c0 = b & 3, c1 = (b >> 2) & 3, c2 = (b >> 4) & 3, c3 = (b >> 6) & 3;
                if (e & 1u) { i0 -= c0; i1 -= c1; i2 -= c2; i3 -= c3; }
                else        { i0 += c0; i1 += c1; i2 += c2; i3 += c3; }
            }
            float4 r;
            r.x = ((float)i0 * ACTS) * s4;
            r.y = ((float)i1 * ACTS) * s4;
            r.z = ((float)i2 * ACTS) * s4;
            r.w = ((float)i3 * ACTS) * s4;
            ((float4*)outs)[o * 33 + lane] = r;
        }
    }
    __syncthreads();

    {
        int row = (g << 2) + (lane >> 3);
        int ob = (lane & 7) << 2;
        float* orow = out + (size_t)(row0 + row) * 128;
        #pragma unroll
        for (int i = 0; i < 4; i++) {
            int o = ob + (i << 5);
            float4 v;
            v.x = outs[(o + 0) * 132 + row];
            v.y = outs[(o + 1) * 132 + row];
            v.z = outs[(o + 2) * 132 + row];
            v.w = outs[(o + 3) * 132 + row];
            *(float4*)(orow + o) = v;
        }
    }
}

__global__ void __launch_bounds__(THREADS, 1) mlp_main(
    const float* __restrict__ x,
    const float* __restrict__ b1a, const float* __restrict__ b1b,
    const float* __restrict__ b2,  const float* __restrict__ b3,
    float* __restrict__ out)
{
    extern __shared__ unsigned char smem[];
    int* s_off = (int*)(smem + 161568);
    unsigned int* s_list = (unsigned int*)(smem + 171048);

    const int tid = threadIdx.x;
    const int row0 = blockIdx.x << 7;

    for (int i = tid; i <= NSEG; i += THREADS) s_off[i] = d_off[i];
    const int total = d_off[NSEG];
    const bool use_sm = (total <= LIST_CAP);
    if (use_sm) {
        const unsigned int* src = (const unsigned int*)d_list;
        int n32 = (total + 1) >> 1;
        for (int i = tid; i < n32; i += THREADS) s_list[i] = src[i];
    }
    __syncthreads();

    if (use_sm) mlp_body<true>(smem, x, b1a, b1b, b2, b3, out, row0);
    else        mlp_body<false>(smem, x, b1a, b1b, b2, b3, out, row0);
}

extern "C" void kernel_launch(void* const* d_in, const int* in_sizes, int n_in,
                              void* d_out, int out_size)
{
    const float* x    = (const float*)d_in[0];
    const float* W1a  = (const float*)d_in[1];
    const float* b1a  = (const float*)d_in[2];
    const float* W1b  = (const float*)d_in[3];
    const float* b1b  = (const float*)d_in[4];
    const float* W2   = (const float*)d_in[5];
    const float* b2   = (const float*)d_in[6];
    const float* W3   = (const float*)d_in[7];
    const float* b3   = (const float*)d_in[8];
    const float* Wout = (const float*)d_in[9];
    float* out = (float*)d_out;

    prep_scale<<<160, 256>>>(W1a, W1b, W2, W3, Wout);
    prep_count<<<NSEG / 8, 256>>>(W1a, W1b, W2, W3, Wout);
    prep_scanfill<<<148, 256>>>(W1a, W1b, W2, W3, Wout);

    cudaFuncSetAttribute(mlp_main, cudaFuncAttributeMaxDynamicSharedMemorySize, SMEM_BYTES);
    mlp_main<<<GRID, THREADS, SMEM_BYTES>>>(x, b1a, b1b, b2, b3, out);
}

// round 10
// speedup vs baseline: 1.5818x; 1.5818x over previous
#include <cuda_runtime.h>
#include <cstdint>
#include <cstddef>

// segments: L1: ((m*4+q)<<8) + (o<<1) + s  -> [0,2048), len 256 (q = 256-col chunk, s = 0 pos / 1 neg)
//  W2: 2048+o (128 segs, len 512)  W3: 2176+o (64)  Wout: 2240+o (128)
#define NSEG     2368
#define SEG_W2   2048
#define SEG_W3   2176
#define SEG_WOUT 2240
#define LIST_MAX 655360
#define LIST_CAP 16384
#define ACTS     1.3333333730697632f
#define THREADS  1024
#define GRID     512            // 32768 / 64 rows per block

__device__ int d_scale_bits[5];
__device__ int d_cnt[NSEG];
__device__ int d_off[NSEG + 1];
__device__ __align__(16) unsigned short d_list[LIST_MAX];

__global__ void prep_scale(const float* __restrict__ W1a, const float* __restrict__ W1b,
                           const float* __restrict__ W2,  const float* __restrict__ W3,
                           const float* __restrict__ Wout)
{
    __shared__ float red[8];
    int m = blockIdx.x >> 5, part = blockIdx.x & 31;
    const float* W; int n;
    switch (m) {
        case 0: W = W1a;  n = 131072; break;
        case 1: W = W1b;  n = 131072; break;
        case 2: W = W2;   n = 65536;  break;
        case 3: W = W3;   n = 8192;   break;
        default: W = Wout; n = 8192;  break;
    }
    int chunk = n >> 5, lo = part * chunk;
    float mx = 0.0f;
    for (int i = lo + threadIdx.x; i < lo + chunk; i += 256)
        mx = fmaxf(mx, fabsf(W[i]));
    #pragma unroll
    for (int o = 16; o; o >>= 1) mx = fmaxf(mx, __shfl_xor_sync(~0u, mx, o));
    if ((threadIdx.x & 31) == 0) red[threadIdx.x >> 5] = mx;
    __syncthreads();
    if (threadIdx.x < 32) {
        float v = (threadIdx.x < 8) ? red[threadIdx.x] : 0.0f;
        #pragma unroll
        for (int o = 4; o; o >>= 1) v = fmaxf(v, __shfl_xor_sync(~0u, v, o));
        if (threadIdx.x == 0) atomicMax(&d_scale_bits[m], __float_as_int(v));
    }
}

struct SegInfo { const float* rowp; int len; float s; bool l1; int sign; };

__device__ __forceinline__ SegInfo seg_decode(int seg,
    const float* W1a, const float* W1b, const float* W2,
    const float* W3, const float* Wout)
{
    SegInfo r; r.sign = 0;
    if (seg < SEG_W2) {
        int m = seg >> 10, q = (seg >> 8) & 3, o = (seg >> 1) & 127;
        r.sign = seg & 1;
        r.rowp = (m ? W1b : W1a) + o * 1024 + q * 256;
        r.len = 256; r.s = __int_as_float(d_scale_bits[m]); r.l1 = true;
    } else if (seg < SEG_W3) {
        r.rowp = W2 + (seg - SEG_W2) * 512;
        r.len = 512; r.s = __int_as_float(d_scale_bits[2]); r.l1 = false;
    } else if (seg < SEG_WOUT) {
        r.rowp = W3 + (seg - SEG_W3) * 128;
        r.len = 128; r.s = __int_as_float(d_scale_bits[3]); r.l1 = false;
    } else {
        r.rowp = Wout + (seg - SEG_WOUT) * 64;
        r.len = 64; r.s = __int_as_float(d_scale_bits[4]); r.l1 = false;
    }
    return r;
}

__global__ void prep_count(const float* __restrict__ W1a, const float* __restrict__ W1b,
                           const float* __restrict__ W2,  const float* __restrict__ W3,
                           const float* __restrict__ Wout)
{
    int lane = threadIdx.x & 31;
    int seg = blockIdx.x * 8 + (threadIdx.x >> 5);
    if (seg >= NSEG) return;
    SegInfo si = seg_decode(seg, W1a, W1b, W2, W3, Wout);
    int cnt = 0;
    for (int j0 = 0; j0 < si.len; j0 += 32) {
        float q = rintf(__fdiv_rn(si.rowp[j0 + lane], si.s));
        bool nz = si.l1 ? (si.sign ? (q < 0.0f) : (q > 0.0f)) : (q != 0.0f);
        cnt += __popc(__ballot_sync(~0u, nz));
    }
    if (lane == 0) d_cnt[seg] = (cnt + 3) & ~3;   // pad to 4 (0 stays 0)
}

// entries: L1: idx*66 (u16; pad = 16896 = 256*66 -> zero column)
//          W2/W3/Wout (R5 verbatim): (idx<<2)|cls  (cls 1=+,2=-,0=pad)
__global__ void prep_scanfill(const float* __restrict__ W1a, const float* __restrict__ W1b,
                              const float* __restrict__ W2,  const float* __restrict__ W3,
                              const float* __restrict__ Wout)
{
    __shared__ int s_off[NSEG + 1];
    __shared__ int warpsum[8];
    int tid = threadIdx.x, lane = tid & 31, w = tid >> 5;
    {
        int base = tid * 10, v[10], s = 0;
        #pragma unroll
        for (int k = 0; k < 10; k++) {
            int idx = base + k;
            int c = (idx < NSEG) ? d_cnt[idx] : 0;
            v[k] = s; s += c;
        }
        int incl = s;
        #pragma unroll
        for (int o = 1; o < 32; o <<= 1) {
            int t = __shfl_up_sync(~0u, incl, o);
            if (lane >= o) incl += t;
        }
        if (lane == 31) warpsum[w] = incl;
        __syncthreads();
        if (w == 0 && lane < 8) {
            int ws = warpsum[lane];
            #pragma unroll
            for (int o = 1; o < 8; o <<= 1) {
                int t = __shfl_up_sync(0xffu, ws, o);
                if (lane >= o) ws += t;
            }
            warpsum[lane] = ws;
        }
        __syncthreads();
        int excl = incl - s + (w ? warpsum[w - 1] : 0);
        #pragma unroll
        for (int k = 0; k < 10; k++) {
            int idx = base + k;
            if (idx <= NSEG) s_off[idx] = excl + v[k];
        }
        __syncthreads();
    }
    if (blockIdx.x == 0)
        for (int i = tid; i <= NSEG; i += 256) d_off[i] = s_off[i];

    for (int seg = blockIdx.x * 8 + w; seg < NSEG; seg += gridDim.x * 8) {
        SegInfo si = seg_decode(seg, W1a, W1b, W2, W3, Wout);
        int base = s_off[seg];
        for (int j0 = 0; j0 < si.len; j0 += 32) {
            float q = rintf(__fdiv_rn(si.rowp[j0 + lane], si.s));
            bool nz = si.l1 ? (si.sign ? (q < 0.0f) : (q > 0.0f)) : (q != 0.0f);
            unsigned bal = __ballot_sync(~0u, nz);
            if (nz) {
                int pos = base + __popc(bal & ((1u << lane) - 1u));
                int idx = j0 + lane;
                unsigned e = si.l1 ? (unsigned)(idx * 66)
                                   : (unsigned)((idx << 2) | (q > 0.0f ? 1 : 2));
                d_list[pos] = (unsigned short)e;
            }
            base += __popc(bal);
        }
        unsigned padv = si.l1 ? 16896u : 0u;
        int end = s_off[seg + 1];
        for (int p = base + lane; p < end; p += 32) d_list[p] = (unsigned short)padv;
    }
}

// smem: XS0@0: 257*66*4 = 67848   XS1@67848 (end 135696)
//  H1@135696: 512*66 = 33792 (end 169488)  H2@169488: 8448 (end 177936)
//  H3@177936: 4224 (end 182160)  OFF@182160: 9476 (end 191636, pad->191640)
//  LIST@191640: 16384*2 = 32768 -> total 224408 ; OUTS aliases XS0
#define SMEM_BYTES 224408

__device__ __forceinline__ float quant_relu_q(float y) {
    float qv = rintf(__fdiv_rn(y, ACTS));
    return fminf(fmaxf(qv, 0.0f), 3.0f);
}
__device__ __forceinline__ int csel(unsigned c, int v) {
    int r = (c == 1u) ? v : 0;
    return (c == 2u) ? -v : r;
}
__device__ __forceinline__ unsigned long long packf2(float lo, float hi) {
    unsigned long long r;
    asm("mov.b64 %0, {%1, %2};" : "=l"(r) : "f"(lo), "f"(hi));
    return r;
}
__device__ __forceinline__ void unpackf2(float& lo, float& hi, unsigned long long v) {
    asm("mov.b64 {%0, %1}, %2;" : "=f"(lo), "=f"(hi) : "l"(v));
}
__device__ __forceinline__ void fma2(unsigned long long& a, unsigned long long w,
                                     unsigned long long v) {
    asm("fma.rn.f32x2 %0, %1, %2, %3;" : "=l"(a) : "l"(w), "l"(v), "l"(a));
}

#define L1MAC(b) { \
    unsigned long long v; \
    asm("ld.shared.b64 %0, [%1];" : "=l"(v) : "r"(curb + (b))); \
    fma2(acc, wpx, v); }
#define L1PACK(pk) { \
    unsigned b0 = (pk.x << 2) & 0x3fffcu, b1 = (pk.x >> 14) & 0x3fffcu; \
    unsigned b2 = (pk.y << 2) & 0x3fffcu, b3 = (pk.y >> 14) & 0x3fffcu; \
    L1MAC(b0); L1MAC(b1); L1MAC(b2); L1MAC(b3); }

template<bool USE_SM>
__device__ __forceinline__ void mlp_body(
    unsigned char* smem,
    const float* __restrict__ x,
    const float* __restrict__ b1a, const float* __restrict__ b1b,
    const float* __restrict__ b2,  const float* __restrict__ b3,
    float* __restrict__ out, int row0)
{
    float* xs0 = (float*)(smem);
    float* xs1 = (float*)(smem + 67848);
    unsigned char* h1s = smem + 135696;
    unsigned char* h2s = smem + 169488;
    unsigned char* h3s = smem + 177936;
    int* s_off = (int*)(smem + 182160);
    const unsigned short* lst = USE_SM ? (const unsigned short*)(smem + 191640)
                                       : (const unsigned short*)d_list;
    float* outs = (float*)(smem);   // alias XS0, layout [row][o] stride 132

    const int tid = threadIdx.x, lane = tid & 31, g = tid >> 5;
    const int r2 = lane << 1;
    const int srow = (g << 1) + (lane >> 4);
    const int cl = lane & 15;
    const float* xrow = x + (size_t)(row0 + srow) * 4096;

    const float sc1a = __int_as_float(d_scale_bits[0]);
    const float sc1b = __int_as_float(d_scale_bits[1]);
    const float s2 = __int_as_float(d_scale_bits[2]);
    const float s3 = __int_as_float(d_scale_bits[3]);
    const float s4 = __int_as_float(d_scale_bits[4]);

    // zero column (col 256) in both buffers
    if (tid < 66) xs0[16896 + tid] = 0.0f;
    else if (tid < 132) xs1[16896 + tid - 66] = 0.0f;

    float pf[16];
    #pragma unroll
    for (int k = 0; k < 16; k++) pf[k] = __ldcs(xrow + cl + (k << 4));
    #pragma unroll
    for (int k = 0; k < 16; k++) xs0[(cl + (k << 4)) * 66 + srow] = pf[k];
    __syncthreads();
    #pragma unroll
    for (int k = 0; k < 16; k++) pf[k] = __ldcs(xrow + 256 + cl + (k << 4));

    unsigned long long accp[4];
    #pragma unroll
    for (int j = 0; j < 4; j++) accp[j] = 0ull;

    // ---- layer 1: 16 tiles [64 rows x 256 cols], pos/neg split, f32x2 FMA ----
    for (int t = 0; t < 16; ++t) {
        const int branch = t >> 2, q = t & 3, m = branch & 1;
        const unsigned curb0 = (unsigned)__cvta_generic_to_shared(
                                   ((t & 1) ? xs1 : xs0)) + (unsigned)(r2 << 2);
        const float sc = m ? sc1b : sc1a;
        const unsigned long long wpos = packf2(sc, sc);
        const unsigned long long wneg = packf2(-sc, -sc);

        #pragma unroll
        for (int j = 0; j < 4; j++) {
            int sb = (((m << 2) + q) << 8) + (((g << 2) + j) << 1);
            int p0 = s_off[sb], p1 = s_off[sb + 1], p2 = s_off[sb + 2];
            unsigned long long acc = accp[j];
            const unsigned curb = curb0;
            {
                unsigned long long wpx = wpos;
                for (int p = p0; p < p1; p += 4) {
                    uint2 pk = *(const uint2*)(lst + p);
                    L1PACK(pk);
                }
                wpx = wneg;
                for (int p = p1; p < p2; p += 4) {
                    uint2 pk = *(const uint2*)(lst + p);
                    L1PACK(pk);
                }
            }
            accp[j] = acc;
        }

        if (q == 3) {
            const float* bb = m ? b1b : b1a;
            #pragma unroll
            for (int j = 0; j < 4; j++) {
                int o = (g << 2) + j;
                float bv = bb[o];
                float a0, a1; unpackf2(a0, a1, accp[j]);
                unsigned c0 = (unsigned)(int)quant_relu_q(a0 + bv);
                unsigned c1 = (unsigned)(int)quant_relu_q(a1 + bv);
                *(unsigned short*)(h1s + (branch * 128 + o) * 66 + r2) =
                    (unsigned short)(c0 | (c1 << 8));
                accp[j] = 0ull;
            }
        }

        if (t + 1 < 16) {
            float* nxt = (t & 1) ? xs0 : xs1;
            #pragma unroll
            for (int k = 0; k < 16; k++)
                nxt[(cl + (k << 4)) * 66 + srow] = pf[k];
            __syncthreads();
            if (t + 2 < 16) {
                const float* xb = xrow + (t + 2) * 256;
                #pragma unroll
                for (int k = 0; k < 16; k++)
                    pf[k] = __ldcs(xb + cl + (k << 4));
            }
        }
    }
    __syncthreads();

    // ---- layer 2: 512 -> 128 (R5 verbatim) ----
    #pragma unroll
    for (int j = 0; j < 4; j++) {
        int o = (g << 2) + j;
        int seg = SEG_W2 + o;
        int p0 = s_off[seg], p1 = s_off[seg + 1];
        int is0 = 0, is1 = 0;
        for (int p = p0; p < p1; p += 4) {
            uint2 pk = *(const uint2*)(lst + p);
            unsigned e0 = pk.x & 0xffffu, e1 = pk.x >> 16;
            unsigned e2 = pk.y & 0xffffu, e3 = pk.y >> 16;
            unsigned c0 = *(const unsigned short*)(h1s + (e0 >> 2) * 66 + r2);
            unsigned c1 = *(const unsigned short*)(h1s + (e1 >> 2) * 66 + r2);
            unsigned c2 = *(const unsigned short*)(h1s + (e2 >> 2) * 66 + r2);
            unsigned c3 = *(const unsigned short*)(h1s + (e3 >> 2) * 66 + r2);
            is0 += csel(e0 & 3u, (int)(c0 & 0xffu)) + csel(e1 & 3u, (int)(c1 & 0xffu))
                 + csel(e2 & 3u, (int)(c2 & 0xffu)) + csel(e3 & 3u, (int)(c3 & 0xffu));
            is1 += csel(e0 & 3u, (int)(c0 >> 8)) + csel(e1 & 3u, (int)(c1 >> 8))
                 + csel(e2 & 3u, (int)(c2 >> 8)) + csel(e3 & 3u, (int)(c3 >> 8));
        }
        float bv = b2[o];
        unsigned q0 = (unsigned)(int)quant_relu_q(fmaf((float)is0 * ACTS, s2, bv));
        unsigned q1 = (unsigned)(int)quant_relu_q(fmaf((float)is1 * ACTS, s2, bv));
        *(unsigned short*)(h2s + o * 66 + r2) = (unsigned short)(q0 | (q1 << 8));
    }
    __syncthreads();

    // ---- layer 3: 128 -> 64 ----
    #pragma unroll
    for (int j = 0; j < 2; j++) {
        int o = (g << 1) + j;
        int seg = SEG_W3 + o;
        int p0 = s_off[seg], p1 = s_off[seg + 1];
        int is0 = 0, is1 = 0;
        for (int p = p0; p < p1; p += 4) {
            uint2 pk = *(const uint2*)(lst + p);
            unsigned e0 = pk.x & 0xffffu, e1 = pk.x >> 16;
            unsigned e2 = pk.y & 0xffffu, e3 = pk.y >> 16;
            unsigned c0 = *(const unsigned short*)(h2s + (e0 >> 2) * 66 + r2);
            unsigned c1 = *(const unsigned short*)(h2s + (e1 >> 2) * 66 + r2);
            unsigned c2 = *(const unsigned short*)(h2s + (e2 >> 2) * 66 + r2);
            unsigned c3 = *(const unsigned short*)(h2s + (e3 >> 2) * 66 + r2);
            is0 += csel(e0 & 3u, (int)(c0 & 0xffu)) + csel(e1 & 3u, (int)(c1 & 0xffu))
                 + csel(e2 & 3u, (int)(c2 & 0xffu)) + csel(e3 & 3u, (int)(c3 & 0xffu));
            is1 += csel(e0 & 3u, (int)(c0 >> 8)) + csel(e1 & 3u, (int)(c1 >> 8))
                 + csel(e2 & 3u, (int)(c2 >> 8)) + csel(e3 & 3u, (int)(c3 >> 8));
        }
        float bv = b3[o];
        unsigned q0 = (unsigned)(int)quant_relu_q(fmaf((float)is0 * ACTS, s3, bv));
        unsigned q1 = (unsigned)(int)quant_relu_q(fmaf((float)is1 * ACTS, s3, bv));
        *(unsigned short*)(h3s + o * 66 + r2) = (unsigned short)(q0 | (q1 << 8));
    }
    __syncthreads();

    // ---- output layer: 64 -> 128, no bias ----
    #pragma unroll
    for (int j = 0; j < 4; j++) {
        int o = (g << 2) + j;
        int seg = SEG_WOUT + o;
        int p0 = s_off[seg], p1 = s_off[seg + 1];
        int is0 = 0, is1 = 0;
        for (int p = p0; p < p1; p += 4) {
            uint2 pk = *(const uint2*)(lst + p);
            unsigned e0 = pk.x & 0xffffu, e1 = pk.x >> 16;
            unsigned e2 = pk.y & 0xffffu, e3 = pk.y >> 16;
            unsigned c0 = *(const unsigned short*)(h3s + (e0 >> 2) * 66 + r2);
            unsigned c1 = *(const unsigned short*)(h3s + (e1 >> 2) * 66 + r2);
            unsigned c2 = *(const unsigned short*)(h3s + (e2 >> 2) * 66 + r2);
            unsigned c3 = *(const unsigned short*)(h3s + (e3 >> 2) * 66 + r2);
            is0 += csel(e0 & 3u, (int)(c0 & 0xffu)) + csel(e1 & 3u, (int)(c1 & 0xffu))
                 + csel(e2 & 3u, (int)(c2 & 0xffu)) + csel(e3 & 3u, (int)(c3 & 0xffu));
            is1 += csel(e0 & 3u, (int)(c0 >> 8)) + csel(e1 & 3u, (int)(c1 >> 8))
                 + csel(e2 & 3u, (int)(c2 >> 8)) + csel(e3 & 3u, (int)(c3 >> 8));
        }
        outs[(r2 + 0) * 132 + o] = ((float)is0 * ACTS) * s4;
        outs[(r2 + 1) * 132 + o] = ((float)is1 * ACTS) * s4;
    }
    __syncthreads();

    #pragma unroll
    for (int k = 0; k < 2; k++) {
        int qi = tid + (k << 10);
        int rr = qi >> 5, c4 = qi & 31;
        float4 v = *(const float4*)&outs[rr * 132 + (c4 << 2)];
        *(float4*)&out[(size_t)(row0 + rr) * 128 + (c4 << 2)] = v;
    }
}

__global__ void __launch_bounds__(THREADS, 1) mlp_main(
    const float* __restrict__ x,
    const float* __restrict__ b1a, const float* __restrict__ b1b,
    const float* __restrict__ b2,  const float* __restrict__ b3,
    float* __restrict__ out)
{
    extern __shared__ unsigned char smem[];
    int* s_off = (int*)(smem + 182160);
    unsigned int* s_list = (unsigned int*)(smem + 191640);

    const int tid = threadIdx.x;
    const int row0 = blockIdx.x << 6;

    for (int i = tid; i <= NSEG; i += THREADS) s_off[i] = d_off[i];
    const int total = d_off[NSEG];
    const bool use_sm = (total <= LIST_CAP);
    if (use_sm) {
        const unsigned int* src = (const unsigned int*)d_list;
        int n32 = (total + 1) >> 1;
        for (int i = tid; i < n32; i += THREADS) s_list[i] = src[i];
    }
    __syncthreads();

    if (use_sm) mlp_body<true>(smem, x, b1a, b1b, b2, b3, out, row0);
    else        mlp_body<false>(smem, x, b1a, b1b, b2, b3, out, row0);
}

extern "C" void kernel_launch(void* const* d_in, const int* in_sizes, int n_in,
                              void* d_out, int out_size)
{
    const float* x    = (const float*)d_in[0];
    const float* W1a  = (const float*)d_in[1];
    const float* b1a  = (const float*)d_in[2];
    const float* W1b  = (const float*)d_in[3];
    const float* b1b  = (const float*)d_in[4];
    const float* W2   = (const float*)d_in[5];
    const float* b2   = (const float*)d_in[6];
    const float* W3   = (const float*)d_in[7];
    const float* b3   = (const float*)d_in[8];
    const float* Wout = (const float*)d_in[9];
    float* out = (float*)d_out;

    prep_scale<<<160, 256>>>(W1a, W1b, W2, W3, Wout);
    prep_count<<<NSEG / 8, 256>>>(W1a, W1b, W2, W3, Wout);
    prep_scanfill<<<148, 256>>>(W1a, W1b, W2, W3, Wout);

    cudaFuncSetAttribute(mlp_main, cudaFuncAttributeMaxDynamicSharedMemorySize, SMEM_BYTES);
    mlp_main<<<GRID, THREADS, SMEM_BYTES>>>(x, b1a, b1b, b2, b3, out);
}